// round 2
// baseline (speedup 1.0000x reference)
#include <cuda_runtime.h>
#include <math_constants.h>

#define NN 100000
#define NE 1000000
#define DD 64
#define CAP 128

// ---- static scratch (no allocation allowed) ----
__device__ __align__(16) float d_h[NN * DD];   // projected features per layer
__device__ __align__(16) float d_x[NN * DD];   // layer ping buffer
__device__ float d_asrc[NN];
__device__ float d_adst[NN];
__device__ int   d_rowstart[NN + 1];
__device__ int   d_cursor[NN];
__device__ int   d_colsrc[NE];                 // CSR: src per (dst-sorted) edge
__device__ int   d_bsums[128];

// packed fp32x2 FMA (sm_10x): d = a*b + c elementwise on 2 packed f32
#define FMA2(acc, a, b) \
    asm("fma.rn.f32x2 %0, %1, %2, %3;" : "=l"(acc) : "l"(a), "l"(b), "l"(acc))
#define PACKDUP(dst, v) \
    asm("mov.b64 %0, {%1, %1};" : "=l"(dst) : "f"(v))

union U64F2 { unsigned long long u; float f[2]; };

// ================= CSR build (dst invariant across layers) =================

__global__ void zero_counts_k() {
    int i = blockIdx.x * blockDim.x + threadIdx.x;
    if (i < NN) d_cursor[i] = 0;
}

__global__ void hist_k(const int* __restrict__ dst) {
    int e = blockIdx.x * blockDim.x + threadIdx.x;
    if (e < NE) atomicAdd(&d_cursor[dst[e]], 1);
}

__global__ void scan1_k() {
    __shared__ int sh[1024];
    int g = blockIdx.x * 1024 + threadIdx.x;
    int v = (g < NN) ? d_cursor[g] : 0;
    sh[threadIdx.x] = v;
    __syncthreads();
    for (int off = 1; off < 1024; off <<= 1) {
        int t = (threadIdx.x >= off) ? sh[threadIdx.x - off] : 0;
        __syncthreads();
        sh[threadIdx.x] += t;
        __syncthreads();
    }
    if (g < NN) d_rowstart[g] = sh[threadIdx.x] - v;
    if (threadIdx.x == 1023) d_bsums[blockIdx.x] = sh[1023];
}

__global__ void scan2_k(int nb) {
    __shared__ int sh[128];
    int t = threadIdx.x;
    int v = (t < nb) ? d_bsums[t] : 0;
    sh[t] = v;
    __syncthreads();
    for (int off = 1; off < 128; off <<= 1) {
        int u = (t >= off) ? sh[t - off] : 0;
        __syncthreads();
        sh[t] += u;
        __syncthreads();
    }
    if (t < nb) d_bsums[t] = sh[t] - v;
}

__global__ void scan3_k() {
    int g = blockIdx.x * 1024 + threadIdx.x;
    if (g < NN) {
        int r = d_rowstart[g] + d_bsums[blockIdx.x];
        d_rowstart[g] = r;
        d_cursor[g]   = r;
    }
    if (g == 0) d_rowstart[NN] = NE;
}

__global__ void scatter_k(const int* __restrict__ src, const int* __restrict__ dst) {
    int e = blockIdx.x * blockDim.x + threadIdx.x;
    if (e < NE) {
        int p = atomicAdd(&d_cursor[dst[e]], 1);
        d_colsrc[p] = src[e];
    }
}

// ================= GEMM h = x @ W (FFMA2), fused attention logits =================
// 128-row x 64-col tile, 128 threads, 8x8 outputs per thread.
// x staged TRANSPOSED in smem: xsT[k][row], stride 128 (conflict-free reads).
// W pairs read directly as ulonglong2 -> free f32x2 packing of the B operand.

__global__ __launch_bounds__(128) void gemm_attn_k(
        const float* __restrict__ x_ext, int use_internal,
        const float* __restrict__ W,
        const float* __restrict__ att_s, const float* __restrict__ att_d)
{
    const float* __restrict__ x = use_internal ? d_x : x_ext;
    __shared__ __align__(16) float ws[64 * 64];    // 16 KB  [k][c]
    __shared__ __align__(16) float xsT[64 * 128];  // 32 KB  [k][r]
    int tid  = threadIdx.x;
    int row0 = blockIdx.x * 128;

    for (int i = tid; i < 1024; i += 128)
        ((float4*)ws)[i] = ((const float4*)W)[i];
    for (int i = tid; i < 2048; i += 128) {
        int r = i >> 4, c4 = i & 15;
        float4 v = make_float4(0.f, 0.f, 0.f, 0.f);
        int gr = row0 + r;
        if (gr < NN) v = ((const float4*)x)[gr * 16 + c4];
        int c = c4 * 4;
        xsT[(c + 0) * 128 + r] = v.x;
        xsT[(c + 1) * 128 + r] = v.y;
        xsT[(c + 2) * 128 + r] = v.z;
        xsT[(c + 3) * 128 + r] = v.w;
    }
    __syncthreads();

    int tx = (tid & 7) * 8;          // col base (8 cols)
    int ty = (tid >> 3) * 8;         // row base (8 rows)

    unsigned long long acc[8][4];
#pragma unroll
    for (int i = 0; i < 8; i++)
#pragma unroll
        for (int m = 0; m < 4; m++) acc[i][m] = 0ull;

#pragma unroll 4
    for (int k = 0; k < 64; k++) {
        float4 xa = *(const float4*)&xsT[k * 128 + ty];
        float4 xb = *(const float4*)&xsT[k * 128 + ty + 4];
        ulonglong2 wA = *(const ulonglong2*)&ws[k * 64 + tx];
        ulonglong2 wB = *(const ulonglong2*)&ws[k * 64 + tx + 4];
        float xv[8] = {xa.x, xa.y, xa.z, xa.w, xb.x, xb.y, xb.z, xb.w};
#pragma unroll
        for (int i = 0; i < 8; i++) {
            unsigned long long xp;
            PACKDUP(xp, xv[i]);
            FMA2(acc[i][0], xp, wA.x);
            FMA2(acc[i][1], xp, wA.y);
            FMA2(acc[i][2], xp, wB.x);
            FMA2(acc[i][3], xp, wB.y);
        }
    }

    float4 asA = *(const float4*)&att_s[tx];
    float4 asB = *(const float4*)&att_s[tx + 4];
    float4 adA = *(const float4*)&att_d[tx];
    float4 adB = *(const float4*)&att_d[tx + 4];

#pragma unroll
    for (int i = 0; i < 8; i++) {
        U64F2 u0, u1, u2, u3;
        u0.u = acc[i][0]; u1.u = acc[i][1]; u2.u = acc[i][2]; u3.u = acc[i][3];
        float o0 = u0.f[0], o1 = u0.f[1], o2 = u1.f[0], o3 = u1.f[1];
        float o4 = u2.f[0], o5 = u2.f[1], o6 = u3.f[0], o7 = u3.f[1];

        float ps = o0*asA.x + o1*asA.y + o2*asA.z + o3*asA.w
                 + o4*asB.x + o5*asB.y + o6*asB.z + o7*asB.w;
        float pd = o0*adA.x + o1*adA.y + o2*adA.z + o3*adA.w
                 + o4*adB.x + o5*adB.y + o6*adB.z + o7*adB.w;
#pragma unroll
        for (int off = 4; off; off >>= 1) {
            ps += __shfl_xor_sync(0xffffffffu, ps, off, 8);
            pd += __shfl_xor_sync(0xffffffffu, pd, off, 8);
        }
        int gr = row0 + ty + i;
        if (gr < NN) {
            *(float4*)&d_h[gr * 64 + tx]     = make_float4(o0, o1, o2, o3);
            *(float4*)&d_h[gr * 64 + tx + 4] = make_float4(o4, o5, o6, o7);
            if ((tid & 7) == 0) { d_asrc[gr] = ps; d_adst[gr] = pd; }
        }
    }
}

// ================= segment softmax + weighted gather (warp per node) =================
// Single gather pass over a_src; weights cached in smem; 1/denom folded at end.

__global__ __launch_bounds__(256) void aggregate_k(
        const float* __restrict__ bias, float* __restrict__ out_ext, int to_internal)
{
    __shared__ float s_ew[8][CAP];
    __shared__ int   s_cs[8][CAP];
    float* __restrict__ out = to_internal ? d_x : out_ext;
    int w    = threadIdx.x >> 5;
    int lane = threadIdx.x & 31;
    int wid  = blockIdx.x * 8 + w;
    if (wid >= NN) return;

    int beg = d_rowstart[wid];
    int end = d_rowstart[wid + 1];
    int deg = end - beg;
    float2 b2 = *(const float2*)&bias[lane * 2];
    float2* op = (float2*)(out + wid * 64) + lane;

    if (deg == 0) { *op = b2; return; }
    float adv = d_adst[wid];

    if (deg <= CAP) {
        // pass A: gather logits once, cache src + e, per-lane max
        float mxl = -CUDART_INF_F;
        for (int idx = lane; idx < deg; idx += 32) {
            int s = d_colsrc[beg + idx];
            float e = d_asrc[s] + adv;
            e = e > 0.f ? e : 0.2f * e;
            s_cs[w][idx] = s;
            s_ew[w][idx] = e;
            mxl = fmaxf(mxl, e);
        }
#pragma unroll
        for (int off = 16; off; off >>= 1)
            mxl = fmaxf(mxl, __shfl_xor_sync(0xffffffffu, mxl, off));

        // exp in place (each lane rewrites only its own slots) + denominator
        float sml = 0.f;
        for (int idx = lane; idx < deg; idx += 32) {
            float ex = __expf(s_ew[w][idx] - mxl);
            s_ew[w][idx] = ex;
            sml += ex;
        }
#pragma unroll
        for (int off = 16; off; off >>= 1)
            sml += __shfl_xor_sync(0xffffffffu, sml, off);
        float inv = 1.f / (sml + 1e-16f);
        __syncwarp();

        // pass B: weighted coalesced row gather, weights broadcast from smem
        float ax = 0.f, ay = 0.f;
        int j = beg & 0;  // 0
        for (j = 0; j + 2 <= deg; j += 2) {
            int   s0 = s_cs[w][j],     s1 = s_cs[w][j + 1];
            float w0 = s_ew[w][j],     w1 = s_ew[w][j + 1];
            float2 h0 = ((const float2*)(d_h + s0 * 64))[lane];
            float2 h1 = ((const float2*)(d_h + s1 * 64))[lane];
            ax += w0 * h0.x + w1 * h1.x;
            ay += w0 * h0.y + w1 * h1.y;
        }
        if (j < deg) {
            int   s0 = s_cs[w][j];
            float w0 = s_ew[w][j];
            float2 h0 = ((const float2*)(d_h + s0 * 64))[lane];
            ax += w0 * h0.x;
            ay += w0 * h0.y;
        }
        float2 r;
        r.x = ax * inv + b2.x;
        r.y = ay * inv + b2.y;
        *op = r;
    } else {
        // rare fallback: 3-pass global traversal
        float mx = -CUDART_INF_F;
        for (int j = beg + lane; j < end; j += 32) {
            float e = d_asrc[d_colsrc[j]] + adv;
            e = e > 0.f ? e : 0.2f * e;
            mx = fmaxf(mx, e);
        }
#pragma unroll
        for (int off = 16; off; off >>= 1)
            mx = fmaxf(mx, __shfl_xor_sync(0xffffffffu, mx, off));
        float sm = 0.f;
        for (int j = beg + lane; j < end; j += 32) {
            float e = d_asrc[d_colsrc[j]] + adv;
            e = e > 0.f ? e : 0.2f * e;
            sm += __expf(e - mx);
        }
#pragma unroll
        for (int off = 16; off; off >>= 1)
            sm += __shfl_xor_sync(0xffffffffu, sm, off);
        float inv = 1.f / (sm + 1e-16f);
        float ax = 0.f, ay = 0.f;
        for (int j = beg; j < end; j++) {
            int s = d_colsrc[j];
            float e = d_asrc[s] + adv;
            e = e > 0.f ? e : 0.2f * e;
            float wg = __expf(e - mx);
            float2 hv = ((const float2*)(d_h + s * 64))[lane];
            ax += wg * hv.x;
            ay += wg * hv.y;
        }
        float2 r;
        r.x = ax * inv + b2.x;
        r.y = ay * inv + b2.y;
        *op = r;
    }
}

// ================= launch =================

extern "C" void kernel_launch(void* const* d_in, const int* in_sizes, int n_in,
                              void* d_out, int out_size)
{
    const float* g     = (const float*)d_in[0];
    const int*   ei    = (const int*)  d_in[1];
    const float* W     = (const float*)d_in[2];
    const float* att_s = (const float*)d_in[3];
    const float* att_d = (const float*)d_in[4];
    const float* bias  = (const float*)d_in[5];
    float* out = (float*)d_out;

    const int* src = ei;
    const int* dst = ei + NE;

    zero_counts_k<<<(NN + 255) / 256, 256>>>();
    hist_k<<<(NE + 255) / 256, 256>>>(dst);
    int nb = (NN + 1023) / 1024;   // 98
    scan1_k<<<nb, 1024>>>();
    scan2_k<<<1, 128>>>(nb);
    scan3_k<<<nb, 1024>>>();
    scatter_k<<<(NE + 255) / 256, 256>>>(src, dst);

    const int gemm_blocks = (NN + 127) / 128;        // 782
    const int agg_blocks  = (NN + 7) / 8;            // 12500

    for (int L = 0; L < 4; L++) {
        gemm_attn_k<<<gemm_blocks, 128>>>(L == 0 ? g : nullptr, L == 0 ? 0 : 1,
                                          W, att_s, att_d);
        aggregate_k<<<agg_blocks, 256>>>(bias, L == 3 ? out : nullptr,
                                         L == 3 ? 0 : 1);
    }
}